// round 1
// baseline (speedup 1.0000x reference)
#include <cuda_runtime.h>
#include <math_constants.h>

// Problem dims (fixed for this problem)
#define Bb 8
#define Cc 64
#define Nn 4096
#define Oo 64
#define Kk 20

// ---------------- scratch (static device globals; no allocation) ----------------
__device__ float g_d2[(size_t)Bb * Nn * Nn];   // 512 MB pairwise d2
__device__ float g_A [(size_t)Bb * Nn * Oo];   // x . W1
__device__ float g_Q [(size_t)Bb * Nn * Oo];   // x . (W2-W1)
__device__ float g_sq[(size_t)Bb * Nn];        // ||x||^2 per point
__device__ int   g_idx[(size_t)Bb * Nn * Kk];  // knn indices
__device__ float g_sum[Oo];
__device__ float g_sumsq[Oo];

// ---------------- k0: projections A,Q + squared norms + zero stats ----------------
__global__ void k0_precompute(const float* __restrict__ x, const float* __restrict__ W) {
    __shared__ float Ws[Oo * 2 * Cc]; // 8192 floats = 32 KB
    int tid = threadIdx.x; // 128 threads
    for (int t = tid; t < Oo * 2 * Cc; t += 128) Ws[t] = W[t];
    if (blockIdx.x == 0 && tid < Oo) { g_sum[tid] = 0.f; g_sumsq[tid] = 0.f; }
    __syncthreads();

    int b = blockIdx.x >> 5;                       // 32 blocks per batch
    int n = ((blockIdx.x & 31) << 7) + tid;        // point id
    const float* xb = x + (size_t)b * Cc * Nn + n;

    float xv[Cc];
#pragma unroll
    for (int c = 0; c < Cc; c++) xv[c] = xb[(size_t)c * Nn];

    float sq = 0.f;
#pragma unroll
    for (int c = 0; c < Cc; c++) sq = fmaf(xv[c], xv[c], sq);
    g_sq[b * Nn + n] = sq;

    size_t rowoff = ((size_t)(b * Nn + n)) * Oo;
#pragma unroll 1
    for (int og = 0; og < Oo; og += 4) {
        float a[4] = {0.f, 0.f, 0.f, 0.f};
        float q[4] = {0.f, 0.f, 0.f, 0.f};
#pragma unroll
        for (int c = 0; c < Cc; c++) {
            float xc = xv[c];
#pragma unroll
            for (int u = 0; u < 4; u++) {
                float w1 = Ws[(og + u) * 128 + c];
                float w2 = Ws[(og + u) * 128 + 64 + c];
                a[u] = fmaf(xc, w1, a[u]);
                q[u] = fmaf(xc, w2 - w1, q[u]);
            }
        }
        *(float4*)(&g_A[rowoff + og]) = make_float4(a[0], a[1], a[2], a[3]);
        *(float4*)(&g_Q[rowoff + og]) = make_float4(q[0], q[1], q[2], q[3]);
    }
}

// ---------------- k1: pairwise d2 GEMM (128x128 tile, 8x8 micro-tile) ----------------
__global__ void k1_dist(const float* __restrict__ x) {
    extern __shared__ float sm[];
    float* Qs = sm;              // [64][128]
    float* Ks = sm + 64 * 128;   // [64][128]
    int tid = threadIdx.x;       // 256
    int b = blockIdx.z;
    int q0 = blockIdx.y << 7, k0 = blockIdx.x << 7;
    const float* xb = x + (size_t)b * Cc * Nn;

    for (int t = tid; t < 64 * 32; t += 256) {
        int c = t >> 5, i4 = (t & 31) << 2;
        *(float4*)(Qs + c * 128 + i4) = *(const float4*)(xb + (size_t)c * Nn + q0 + i4);
        *(float4*)(Ks + c * 128 + i4) = *(const float4*)(xb + (size_t)c * Nn + k0 + i4);
    }
    __syncthreads();

    int tx = tid & 15, ty = tid >> 4;
    float acc[8][8];
#pragma unroll
    for (int i = 0; i < 8; i++)
#pragma unroll
        for (int j = 0; j < 8; j++) acc[i][j] = 0.f;

#pragma unroll 8
    for (int c = 0; c < 64; c++) {
        float4 a0 = *(float4*)(Qs + c * 128 + ty * 8);
        float4 a1 = *(float4*)(Qs + c * 128 + ty * 8 + 4);
        float4 b0 = *(float4*)(Ks + c * 128 + tx * 8);
        float4 b1 = *(float4*)(Ks + c * 128 + tx * 8 + 4);
        float av[8] = {a0.x, a0.y, a0.z, a0.w, a1.x, a1.y, a1.z, a1.w};
        float bv[8] = {b0.x, b0.y, b0.z, b0.w, b1.x, b1.y, b1.z, b1.w};
#pragma unroll
        for (int i = 0; i < 8; i++)
#pragma unroll
            for (int j = 0; j < 8; j++) acc[i][j] = fmaf(av[i], bv[j], acc[i][j]);
    }

    const float* sqb = g_sq + b * Nn;
    float sqq[8], sqk[8];
#pragma unroll
    for (int i = 0; i < 8; i++) sqq[i] = sqb[q0 + ty * 8 + i];
#pragma unroll
    for (int j = 0; j < 8; j++) sqk[j] = sqb[k0 + tx * 8 + j];

#pragma unroll
    for (int i = 0; i < 8; i++) {
        size_t off = ((size_t)(b * Nn + q0 + ty * 8 + i)) * Nn + k0 + tx * 8;
        float r[8];
#pragma unroll
        for (int j = 0; j < 8; j++) r[j] = fmaf(-2.f, acc[i][j], sqq[i] + sqk[j]);
        *(float4*)(g_d2 + off)     = make_float4(r[0], r[1], r[2], r[3]);
        *(float4*)(g_d2 + off + 4) = make_float4(r[4], r[5], r[6], r[7]);
    }
}

// ---------------- k2: warp-per-row top-20 (smallest d2) ----------------
__global__ void k2_topk() {
    int row  = (blockIdx.x << 2) + (threadIdx.x >> 5);  // 0..32767
    int lane = threadIdx.x & 31;
    const float* rp = g_d2 + (size_t)row * Nn;

    float td[20]; int ti[20];
#pragma unroll
    for (int s = 0; s < 20; s++) { int j = (s << 5) + lane; td[s] = rp[j]; ti[s] = j; }

    float cm = td[0]; int cp = 0;
#pragma unroll
    for (int u = 1; u < 20; u++) if (td[u] > cm) { cm = td[u]; cp = u; }

    for (int s = 20; s < Nn / 32; s++) {
        int j = (s << 5) + lane;
        float d = rp[j];
        if (d < cm) {
#pragma unroll
            for (int u = 0; u < 20; u++) if (u == cp) { td[u] = d; ti[u] = j; }
            cm = td[0]; cp = 0;
#pragma unroll
            for (int u = 1; u < 20; u++) if (td[u] > cm) { cm = td[u]; cp = u; }
        }
    }

    // local min (value, global idx tie-break, slot)
    float lmv = td[0]; int lgi = ti[0]; int lsl = 0;
#pragma unroll
    for (int u = 1; u < 20; u++)
        if (td[u] < lmv || (td[u] == lmv && ti[u] < lgi)) { lmv = td[u]; lgi = ti[u]; lsl = u; }

    int* outp = g_idx + (size_t)row * Kk;
    for (int r = 0; r < Kk; r++) {
        float v = lmv; int gi = lgi;
#pragma unroll
        for (int o = 16; o; o >>= 1) {
            float v2 = __shfl_xor_sync(0xffffffffu, v, o);
            int   g2 = __shfl_xor_sync(0xffffffffu, gi, o);
            if (v2 < v || (v2 == v && g2 < gi)) { v = v2; gi = g2; }
        }
        if (gi == lgi) {  // unique winner: global indices are disjoint across lanes
            outp[r] = gi;
#pragma unroll
            for (int u = 0; u < 20; u++) if (u == lsl) td[u] = CUDART_INF_F;
            lmv = td[0]; lgi = ti[0]; lsl = 0;
#pragma unroll
            for (int u = 1; u < 20; u++)
                if (td[u] < lmv || (td[u] == lmv && ti[u] < lgi)) { lmv = td[u]; lgi = ti[u]; lsl = u; }
        }
    }
}

// ---------------- k3: BN statistics (sum, sumsq per channel) ----------------
__global__ void k3_stats() {
    __shared__ float s0s[4][64];
    __shared__ float s1s[4][64];
    int tid = threadIdx.x;              // 256
    int o = tid & 63, g = tid >> 6;
    int b = blockIdx.x >> 6;            // 64 blocks per batch
    int n0 = (blockIdx.x & 63) << 6;    // 64 points per block

    float s0 = 0.f, s1 = 0.f;
    for (int p = g; p < 64; p += 4) {
        int rown = b * Nn + n0 + p;
        float qv = g_Q[(size_t)rown * Oo + o];
        const int* ip = g_idx + (size_t)rown * Kk;
#pragma unroll
        for (int k = 0; k < Kk; k++) {
            int j = ip[k];
            float h = g_A[((size_t)(b * Nn + j)) * Oo + o] + qv;
            s0 += h;
            s1 = fmaf(h, h, s1);
        }
    }
    s0s[g][o] = s0; s1s[g][o] = s1;
    __syncthreads();
    if (tid < 64) {
        float t0 = s0s[0][tid] + s0s[1][tid] + s0s[2][tid] + s0s[3][tid];
        float t1 = s1s[0][tid] + s1s[1][tid] + s1s[2][tid] + s1s[3][tid];
        atomicAdd(&g_sum[tid], t0);
        atomicAdd(&g_sumsq[tid], t1);
    }
}

// ---------------- k4: normalize + leaky relu + max over k + transpose ----------------
__global__ void k4_out(const float* __restrict__ gamma, const float* __restrict__ beta,
                       float* __restrict__ out) {
    __shared__ float sc[64];
    __shared__ float sh[64];
    __shared__ float ob[64 * 65];
    int tid = threadIdx.x;              // 256
    if (tid < 64) {
        const float inv = 1.f / (float)((size_t)Bb * Nn * Kk);
        float m = g_sum[tid] * inv;
        float v = g_sumsq[tid] * inv - m * m;
        float s = gamma[tid] * rsqrtf(v + 1e-5f);
        sc[tid] = s;
        sh[tid] = fmaf(-m, s, beta[tid]);
    }
    __syncthreads();

    int o = tid & 63, g = tid >> 6;
    int b = blockIdx.x >> 6, n0 = (blockIdx.x & 63) << 6;
    float scale = sc[o], shift = sh[o];

    for (int p = g; p < 64; p += 4) {
        int rown = b * Nn + n0 + p;
        float qv = g_Q[(size_t)rown * Oo + o];
        const int* ip = g_idx + (size_t)rown * Kk;
        float m = -CUDART_INF_F;
#pragma unroll
        for (int k = 0; k < Kk; k++) {
            int j = ip[k];
            float h = g_A[((size_t)(b * Nn + j)) * Oo + o] + qv;
            float hn = fmaf(h, scale, shift);
            float a = (hn >= 0.f) ? hn : 0.2f * hn;
            m = fmaxf(m, a);
        }
        ob[o * 65 + p] = m;
    }
    __syncthreads();

    float* op = out + (size_t)b * Oo * Nn + n0;
    for (int t = tid; t < 64 * 64; t += 256) {
        int oo = t >> 6, p = t & 63;
        op[(size_t)oo * Nn + p] = ob[oo * 65 + p];
    }
}

// ---------------- launch ----------------
extern "C" void kernel_launch(void* const* d_in, const int* in_sizes, int n_in,
                              void* d_out, int out_size) {
    const float* x     = (const float*)d_in[0];
    const float* W     = (const float*)d_in[1];
    const float* gamma = (const float*)d_in[2];
    const float* beta  = (const float*)d_in[3];
    float* out = (float*)d_out;

    cudaFuncSetAttribute(k1_dist, cudaFuncAttributeMaxDynamicSharedMemorySize, 65536);

    k0_precompute<<<256, 128>>>(x, W);
    k1_dist<<<dim3(32, 32, 8), 256, 65536>>>(x);
    k2_topk<<<8192, 128>>>();
    k3_stats<<<512, 256>>>();
    k4_out<<<512, 256>>>(gamma, beta, out);
}